// round 3
// baseline (speedup 1.0000x reference)
#include <cuda_runtime.h>
#include <cuda_bf16.h>

// GATConv heads=1, self loops. h = x@W; out[d] = bias + softmax-weighted sum of h[src].
// Round 3: fused launches, GEMM||CSR overlap via streams, one-pass shfl-broadcast k_gat.

#define IN_DIM   128
#define OUT_DIM  64
#define N_MAX    100000
#define E_MAX    1600000
#define NEG_SLOPE 0.2f
#define SCAN_BLK 1024

// ---------------- device scratch ----------------
__device__ __align__(16) float g_h[(size_t)N_MAX * OUT_DIM];   // 25.6 MB
__device__ float g_as[N_MAX];
__device__ float g_ad[N_MAX];
__device__ int   g_cnt[N_MAX];               // edge count per dst (zero at entry; re-zeroed by k_gat)
__device__ int   g_off[N_MAX];               // block-local exclusive scan
__device__ int   g_start[N_MAX];             // global CSR row start
__device__ int   g_cur[N_MAX];               // fill cursor
__device__ int   g_bsum[256];
__device__ int   g_srcbuf[E_MAX + N_MAX];    // CSR: src per slot

// ---------------- histogram of dst (g_cnt starts zeroed) ----------------
__global__ __launch_bounds__(256) void k_hist(const int* __restrict__ ei, int E) {
    int e = blockIdx.x * blockDim.x + threadIdx.x;
    if (e < E) atomicAdd(&g_cnt[ei[E + e]], 1);
}

// ---------------- scan A: per-block exclusive scan of (cnt+1) ----------------
__global__ __launch_bounds__(SCAN_BLK) void k_scan_a(int N) {
    __shared__ int wsum[32];
    int i = blockIdx.x * SCAN_BLK + threadIdx.x;
    int lane = threadIdx.x & 31, w = threadIdx.x >> 5;
    int v = (i < N) ? (g_cnt[i] + 1) : 0;     // +1: self loop
    int s = v;
#pragma unroll
    for (int o = 1; o < 32; o <<= 1) { int t = __shfl_up_sync(~0u, s, o); if (lane >= o) s += t; }
    if (lane == 31) wsum[w] = s;
    __syncthreads();
    if (w == 0) {
        int t = wsum[lane];
#pragma unroll
        for (int o = 1; o < 32; o <<= 1) { int u = __shfl_up_sync(~0u, t, o); if (lane >= o) t += u; }
        wsum[lane] = t;
    }
    __syncthreads();
    int excl = s - v + (w > 0 ? wsum[w - 1] : 0);
    if (i < N) g_off[i] = excl;
    if (threadIdx.x == SCAN_BLK - 1) g_bsum[blockIdx.x] = wsum[31];
}

// ---------------- scan C: each block derives its own base, writes start/cur ----------------
__global__ __launch_bounds__(SCAN_BLK) void k_scan_c(int N) {
    __shared__ int red[32];
    __shared__ int sbase;
    int t = threadIdx.x, lane = t & 31, w = t >> 5;
    int partial = 0;
    for (int j = t; j < blockIdx.x; j += SCAN_BLK) partial += g_bsum[j];
#pragma unroll
    for (int o = 16; o; o >>= 1) partial += __shfl_xor_sync(~0u, partial, o);
    if (lane == 0) red[w] = partial;
    __syncthreads();
    if (w == 0) {
        int p = red[lane];
#pragma unroll
        for (int o = 16; o; o >>= 1) p += __shfl_xor_sync(~0u, p, o);
        if (lane == 0) sbase = p;
    }
    __syncthreads();
    int i = blockIdx.x * SCAN_BLK + t;
    if (i < N) {
        int s = g_off[i] + sbase;
        g_start[i] = s;
        g_cur[i] = s;
    }
}

// ---------------- fill CSR buckets (edges + self loops) ----------------
__global__ __launch_bounds__(256) void k_fill(const int* __restrict__ ei, int E, int N) {
    int e = blockIdx.x * blockDim.x + threadIdx.x;
    if (e >= E + N) return;
    int src, dst;
    if (e < E) { src = ei[e]; dst = ei[E + e]; }
    else       { src = dst = e - E; }
    int pos = atomicAdd(&g_cur[dst], 1);
    g_srcbuf[pos] = src;
}

// ---------------- GEMM h = x@W + fused attention-logit epilogue ----------------
#define TR 64
#define GEMM_SMEM (IN_DIM * OUT_DIM * 4 + TR * 129 * 4)

__global__ __launch_bounds__(256) void k_gemm(const float* __restrict__ x,
                                              const float* __restrict__ W,
                                              const float* __restrict__ a_src,
                                              const float* __restrict__ a_dst, int N) {
    extern __shared__ float smem[];
    float* Ws = smem;
    float* Xs = smem + IN_DIM * OUT_DIM;
    __shared__ float sPs[4][TR];
    __shared__ float sPd[4][TR];

    int tid = threadIdx.x;
    int rowBase = blockIdx.x * TR;

    for (int i = tid; i < (IN_DIM * OUT_DIM) / 4; i += 256)
        ((float4*)Ws)[i] = ((const float4*)W)[i];

    for (int i = tid; i < (TR * IN_DIM) / 4; i += 256) {
        int r  = i >> 5;
        int kq = i & 31;
        int row = rowBase + r;
        float4 v = (row < N) ? ((const float4*)x)[(size_t)row * 32 + kq]
                             : make_float4(0.f, 0.f, 0.f, 0.f);
        float* p = &Xs[r * 129 + kq * 4];
        p[0] = v.x; p[1] = v.y; p[2] = v.z; p[3] = v.w;
    }
    __syncthreads();

    int w    = tid >> 5;
    int lane = tid & 31;
    int rl   = ((w & 1) << 5) + lane;   // local row 0..63
    int cg   = w >> 1;                  // col group 0..3
    int cb   = cg << 4;                 // col base

    unsigned long long acc[8];
#pragma unroll
    for (int j = 0; j < 8; j++) acc[j] = 0ULL;

    const ulonglong2* Ws2 = (const ulonglong2*)Ws;

#pragma unroll 8
    for (int k = 0; k < IN_DIM; k++) {
        float xv = Xs[rl * 129 + k];
        unsigned long long xp;
        asm("mov.b64 %0, {%1, %1};" : "=l"(xp) : "f"(xv));
        int base = k * 16 + (cb >> 2);
#pragma unroll
        for (int j = 0; j < 4; j++) {
            ulonglong2 ww = Ws2[base + j];
            asm("fma.rn.f32x2 %0, %1, %2, %0;" : "+l"(acc[2 * j])     : "l"(xp), "l"(ww.x));
            asm("fma.rn.f32x2 %0, %1, %2, %0;" : "+l"(acc[2 * j + 1]) : "l"(xp), "l"(ww.y));
        }
    }

    float tmp[16];
#pragma unroll
    for (int j = 0; j < 8; j++) {
        float lo, hi;
        asm("mov.b64 {%0, %1}, %2;" : "=f"(lo), "=f"(hi) : "l"(acc[j]));
        tmp[2 * j] = lo; tmp[2 * j + 1] = hi;
    }

    int row = rowBase + rl;
    if (row < N) {
        float4* hp = (float4*)(g_h + (size_t)row * OUT_DIM + cb);
#pragma unroll
        for (int j = 0; j < 4; j++)
            hp[j] = make_float4(tmp[4 * j], tmp[4 * j + 1], tmp[4 * j + 2], tmp[4 * j + 3]);
    }

    // fused attention logits: ps = h[row]·a_src (this thread's 16-col slice)
    float ps = 0.f, pd = 0.f;
#pragma unroll
    for (int j = 0; j < 16; j++) {
        ps += tmp[j] * __ldg(&a_src[cb + j]);
        pd += tmp[j] * __ldg(&a_dst[cb + j]);
    }
    sPs[cg][rl] = ps;
    sPd[cg][rl] = pd;
    __syncthreads();
    if (tid < TR) {
        int r2 = rowBase + tid;
        if (r2 < N) {
            g_as[r2] = sPs[0][tid] + sPs[1][tid] + sPs[2][tid] + sPs[3][tid];
            g_ad[r2] = sPd[0][tid] + sPd[1][tid] + sPd[2][tid] + sPd[3][tid];
        }
    }
}

// ---------------- one-pass warp-per-dst aggregation ----------------
__global__ __launch_bounds__(256) void k_gat(const float* __restrict__ bias,
                                             float* __restrict__ out, int N) {
    int gw   = (blockIdx.x * blockDim.x + threadIdx.x) >> 5;
    int lane = threadIdx.x & 31;
    if (gw >= N) return;
    int start = g_start[gw];
    int cnt   = g_cnt[gw] + 1;       // + self loop
    if (lane == 0) g_cnt[gw] = 0;    // reset for next graph replay
    float ad  = g_ad[gw];

    float sum = 0.0f;
    float2 acc = make_float2(0.0f, 0.0f);
    const float2* hb = (const float2*)g_h;

    for (int base = 0; base < cnt; base += 32) {
        int i = base + lane;
        int srcl = 0; float exl = 0.0f;
        if (i < cnt) {
            srcl = g_srcbuf[start + i];
            float v = g_as[srcl] + ad;
            v = (v > 0.0f) ? v : NEG_SLOPE * v;
            exl = __expf(v);
        }
        sum += exl;
        int m = min(32, cnt - base);
#pragma unroll 4
        for (int j = 0; j < m; j++) {
            int   s = __shfl_sync(~0u, srcl, j);
            float a = __shfl_sync(~0u, exl, j);
            float2 hv = hb[(size_t)s * 32 + lane];
            acc.x += a * hv.x;
            acc.y += a * hv.y;
        }
    }
#pragma unroll
    for (int o = 16; o; o >>= 1) sum += __shfl_xor_sync(~0u, sum, o);
    float invS = __fdividef(1.0f, sum);

    float2 bv = ((const float2*)bias)[lane];
    float2 r = make_float2(acc.x * invS + bv.x, acc.y * invS + bv.y);
    ((float2*)out)[(size_t)gw * 32 + lane] = r;
}

// ---------------- launcher ----------------
extern "C" void kernel_launch(void* const* d_in, const int* in_sizes, int n_in,
                              void* d_out, int out_size) {
    const float* x     = (const float*)d_in[0];
    const int*   ei    = (const int*)  d_in[1];
    const float* W     = (const float*)d_in[2];
    const float* a_src = (const float*)d_in[3];
    const float* a_dst = (const float*)d_in[4];
    const float* bias  = (const float*)d_in[5];
    float* out = (float*)d_out;

    int N = in_sizes[0] / IN_DIM;
    int E = in_sizes[1] / 2;
    int T = E + N;
    int NB = (N + SCAN_BLK - 1) / SCAN_BLK;

    static cudaStream_t s2;
    static cudaEvent_t evA, evB;
    static bool init_done = false;
    if (!init_done) {
        cudaFuncSetAttribute(k_gemm, cudaFuncAttributeMaxDynamicSharedMemorySize, GEMM_SMEM);
        cudaStreamCreateWithFlags(&s2, cudaStreamNonBlocking);
        cudaEventCreateWithFlags(&evA, cudaEventDisableTiming);
        cudaEventCreateWithFlags(&evB, cudaEventDisableTiming);
        init_done = true;
    }

    // fork: GEMM (+ logits) on s2, CSR build on the main stream
    cudaEventRecord(evA, 0);
    cudaStreamWaitEvent(s2, evA, 0);
    k_gemm<<<(N + TR - 1) / TR, 256, GEMM_SMEM, s2>>>(x, W, a_src, a_dst, N);

    k_hist<<<(E + 255) / 256, 256>>>(ei, E);
    k_scan_a<<<NB, SCAN_BLK>>>(N);
    k_scan_c<<<NB, SCAN_BLK>>>(N);
    k_fill<<<(T + 255) / 256, 256>>>(ei, E, N);

    // join: aggregation needs both CSR and h/as/ad
    cudaEventRecord(evB, s2);
    cudaStreamWaitEvent(0, evB, 0);
    k_gat<<<(N * 32 + 255) / 256, 256>>>(bias, out, N);
}